// round 15
// baseline (speedup 1.0000x reference)
#include <cuda_runtime.h>
#include <cuda_fp16.h>
#include <math.h>

#define Nn 100000
#define Ee 1600000
#define NSCAN (Nn + 1)
#define FIX_MARGIN 3e-3f
#define NB_NODE_W 12500      // Nn*32/256
#define NB_EDGE_T 6250       // Ee/256
#define SCAN_B 98            // ceil(100001/1024)
#define NTILES 1563          // ceil(Nn/64)
#define NB_G1 444            // persistent gemm grid (C=128)
#define NB_G2 592            // persistent gemm grid (C=64)

// ---------------- scratch (__device__ globals; no runtime allocation) ----------------
__device__ __align__(16) float g_h[(size_t)Nn * 128];       // h1 ; layer2: hW2 as fp16
__device__ __align__(16) float g_acc[(size_t)Nn * 128];     // relu(LN(...)) of layer 1
__device__ __align__(16) __half g_xh[(size_t)(Nn + 64) * 128]; // NORMALIZED fp16 (padded)
__device__ __align__(16) float g_w[Ee];                     // sims -> edge weights
__device__ int g_srow[Ee];
__device__ int g_hist[NSCAN];
__device__ int g_ptr[NSCAN];
__device__ int g_pos[Nn];
__device__ int g_agg[SCAN_B];
__device__ int g_flag[SCAN_B];
__device__ float g_rnrm[Nn];                                // 1/max(||f||, eps)
__device__ float g_dra[Nn];
__device__ float g_drb[Nn];
__device__ float g_cnt[Nn];
__device__ float g_d2[Nn];

__device__ __forceinline__ float warp_sum(float v) {
    #pragma unroll
    for (int o = 16; o; o >>= 1) v += __shfl_xor_sync(0xFFFFFFFFu, v, o);
    return v;
}
__device__ __forceinline__ int warp_isum(int v) {
    #pragma unroll
    for (int o = 16; o; o >>= 1) v += __shfl_xor_sync(0xFFFFFFFFu, v, o);
    return v;
}
__device__ __forceinline__ float warp_max(float v) {
    #pragma unroll
    for (int o = 16; o; o >>= 1) v = fmaxf(v, __shfl_xor_sync(0xFFFFFFFFu, v, o));
    return v;
}

// ======================= CSC build ==================
__global__ void hist_kernel(const int* __restrict__ col) {
    int e = blockIdx.x * blockDim.x + threadIdx.x;
    if (e < Ee) atomicAdd(&g_hist[__ldg(col + e)], 1);
}

__global__ void scan_lookback_kernel() {
    __shared__ int wsum[32];
    __shared__ int s_off;
    int tid = threadIdx.x;
    int lane = tid & 31, wid = tid >> 5;
    int b = blockIdx.x;
    int i = b * 1024 + tid;
    int v = (i < NSCAN) ? g_hist[i] : 0;
    int x = v;
    #pragma unroll
    for (int o = 1; o < 32; o <<= 1) {
        int t = __shfl_up_sync(0xFFFFFFFFu, x, o);
        if (lane >= o) x += t;
    }
    if (lane == 31) wsum[wid] = x;
    __syncthreads();
    if (wid == 0) {
        int y = wsum[lane];
        #pragma unroll
        for (int o = 1; o < 32; o <<= 1) {
            int t = __shfl_up_sync(0xFFFFFFFFu, y, o);
            if (lane >= o) y += t;
        }
        wsum[lane] = y;
    }
    __syncthreads();
    int incl = x + (wid ? wsum[wid - 1] : 0);
    if (tid == 0) {
        g_agg[b] = wsum[31];
        __threadfence();
        *((volatile int*)&g_flag[b]) = 1;
    }
    if (tid < 32) {
        volatile int* flag = g_flag;
        volatile int* agg  = g_agg;
        int acc = 0;
        for (int j = lane; j < b; j += 32) {
            while (flag[j] == 0) { }
            acc += agg[j];
        }
        acc = warp_isum(acc);
        if (lane == 0) s_off = acc;
    }
    __syncthreads();
    int excl = incl - v + s_off;
    if (i < NSCAN) {
        g_ptr[i] = excl;
        if (i < Nn) g_pos[i] = excl;
    }
}

// standalone rnrm + normalized fp16 copy (runs on s1, overlaps hist/scan)
__global__ void rnrm_kernel(const float* __restrict__ F, __half* __restrict__ Fh) {
    int n = (blockIdx.x * blockDim.x + threadIdx.x) >> 5;
    int lane = threadIdx.x & 31;
    if (n >= Nn) return;
    float4 v = ((const float4*)F)[(size_t)n * 32 + lane];
    float ss = warp_sum(v.x * v.x + v.y * v.y + v.z * v.z + v.w * v.w);
    float ri = 1.0f / fmaxf(sqrtf(ss), 1e-8f);
    __half2 h0 = __floats2half2_rn(v.x * ri, v.y * ri);
    __half2 h1 = __floats2half2_rn(v.z * ri, v.w * ri);
    uint2 u;
    u.x = *reinterpret_cast<unsigned int*>(&h0);
    u.y = *reinterpret_cast<unsigned int*>(&h1);
    ((uint2*)Fh)[(size_t)n * 32 + lane] = u;
    if (lane == 0) g_rnrm[n] = ri;
}

__global__ void scatter_kernel(const int* __restrict__ row, const int* __restrict__ col) {
    int e = blockIdx.x * blockDim.x + threadIdx.x;
    if (e >= Ee) return;
    int c = __ldg(col + e);
    int p = atomicAdd(&g_pos[c], 1);
    g_srow[p] = __ldg(row + e);
}

// ======================= edge similarity ====================
__device__ __forceinline__ float dot16h2(const uint4& a0, const uint4& a1,
                                         const __half2* fc) {
    __half2 acc = __hmul2(*(const __half2*)&a0.x, fc[0]);
    acc = __hfma2(*(const __half2*)&a0.y, fc[1], acc);
    acc = __hfma2(*(const __half2*)&a0.z, fc[2], acc);
    acc = __hfma2(*(const __half2*)&a0.w, fc[3], acc);
    acc = __hfma2(*(const __half2*)&a1.x, fc[4], acc);
    acc = __hfma2(*(const __half2*)&a1.y, fc[5], acc);
    acc = __hfma2(*(const __half2*)&a1.z, fc[6], acc);
    acc = __hfma2(*(const __half2*)&a1.w, fc[7], acc);
    float2 f = __half22float2(acc);
    return f.x + f.y;
}

__global__ void __launch_bounds__(256, 6)
edge_dot_h(const __half* __restrict__ Fh, const float* __restrict__ F,
           float* __restrict__ dr) {
    int n = (blockIdx.x * blockDim.x + threadIdx.x) >> 5;
    int lane = threadIdx.x & 31;
    if (n >= Nn) return;
    int k = lane & 7;
    int g = lane >> 3;
    unsigned gmask = 0xFFu << (g * 8);
    const uint4* F16 = (const uint4*)Fh;
    uint4 c0 = F16[(size_t)n * 16 + k];
    uint4 c1 = F16[(size_t)n * 16 + k + 8];
    __half2 fc[8];
    fc[0] = *(const __half2*)&c0.x; fc[1] = *(const __half2*)&c0.y;
    fc[2] = *(const __half2*)&c0.z; fc[3] = *(const __half2*)&c0.w;
    fc[4] = *(const __half2*)&c1.x; fc[5] = *(const __half2*)&c1.y;
    fc[6] = *(const __half2*)&c1.z; fc[7] = *(const __half2*)&c1.w;
    int beg = g_ptr[n], end = g_ptr[n + 1];
    for (int i = beg; i < end; i += 4) {
        int j = i + g;
        bool valid = j < end;
        int r = __ldg(g_srow + (valid ? j : end - 1));
        uint4 a0 = F16[(size_t)r * 16 + k];
        uint4 a1 = F16[(size_t)r * 16 + k + 8];
        float s = dot16h2(a0, a1, fc);
        s += __shfl_xor_sync(0xFFFFFFFFu, s, 4);
        s += __shfl_xor_sync(0xFFFFFFFFu, s, 2);
        s += __shfl_xor_sync(0xFFFFFFFFu, s, 1);
        float sim = s;
        if (valid && fabsf(sim - 0.1f) < FIX_MARGIN) {
            const float4* Fr = (const float4*)(F + (size_t)r * 128);
            const float4* Fc = (const float4*)(F + (size_t)n * 128);
            float4 xa = Fr[k],      ya = Fc[k];
            float4 xb = Fr[k + 8],  yb = Fc[k + 8];
            float4 xd = Fr[k + 16], yd = Fc[k + 16];
            float4 xe = Fr[k + 24], ye = Fc[k + 24];
            float t = xa.x * ya.x + xa.y * ya.y + xa.z * ya.z + xa.w * ya.w
                    + xb.x * yb.x + xb.y * yb.y + xb.z * yb.z + xb.w * yb.w
                    + xd.x * yd.x + xd.y * yd.y + xd.z * yd.z + xd.w * yd.w
                    + xe.x * ye.x + xe.y * ye.y + xe.z * ye.z + xe.w * ye.w;
            t += __shfl_xor_sync(gmask, t, 4);
            t += __shfl_xor_sync(gmask, t, 2);
            t += __shfl_xor_sync(gmask, t, 1);
            sim = t * g_rnrm[r] * g_rnrm[n];
        }
        if (valid && k == 0) {
            if (sim >= 0.1f) { g_w[j] = sim; atomicAdd(dr + r, sim); }
            else g_w[j] = 0.0f;
        }
    }
}

// fast-exp edge weights + selfw + gcn degree -> dinv2
__global__ void edge_w_kernel(const float* __restrict__ dr) {
    int n = (blockIdx.x * blockDim.x + threadIdx.x) >> 5;
    int lane = threadIdx.x & 31;
    if (n >= Nn) return;
    int beg = g_ptr[n], end = g_ptr[n + 1];
    float d = dr[n];
    float dc = (d > 0.0f) ? rsqrtf(d) : 0.0f;
    float deg2 = 0.0f;
    int cnt = 0;
    for (int i = beg + lane; i < end; i += 32) {
        float s = g_w[i];
        if (s > 0.0f) {
            cnt++;
            float dg = dr[__ldg(g_srow + i)];
            float w = __expf(rsqrtf(dg) * s * dc);
            g_w[i] = w;
            deg2 += w;
        }
    }
    deg2 = warp_sum(deg2);
    cnt = __reduce_add_sync(0xFFFFFFFFu, cnt);
    if (lane == 0) {
        float selfw = __expf(1.0f / (float)(cnt + 1));
        g_cnt[n] = selfw;
        g_d2[n] = rsqrtf(deg2 + selfw);
    }
}

// ======================= persistent tensor-core GEMM ==================================
__device__ __forceinline__ void ldsm_x4(unsigned& a0, unsigned& a1, unsigned& a2, unsigned& a3,
                                        unsigned addr) {
    asm volatile("ldmatrix.sync.aligned.m8n8.x4.shared.b16 {%0,%1,%2,%3}, [%4];"
                 : "=r"(a0), "=r"(a1), "=r"(a2), "=r"(a3) : "r"(addr));
}
__device__ __forceinline__ void ldsm_x2t(unsigned& b0, unsigned& b1, unsigned addr) {
    asm volatile("ldmatrix.sync.aligned.m8n8.x2.trans.shared.b16 {%0,%1}, [%2];"
                 : "=r"(b0), "=r"(b1) : "r"(addr));
}
__device__ __forceinline__ void mma16816(float& d0, float& d1, float& d2, float& d3,
                                         unsigned a0, unsigned a1, unsigned a2, unsigned a3,
                                         unsigned b0, unsigned b1) {
    asm volatile("mma.sync.aligned.m16n8k16.row.col.f32.f16.f16.f32 "
                 "{%0,%1,%2,%3}, {%4,%5,%6,%7}, {%8,%9}, {%0,%1,%2,%3};"
                 : "+f"(d0), "+f"(d1), "+f"(d2), "+f"(d3)
                 : "r"(a0), "r"(a1), "r"(a2), "r"(a3), "r"(b0), "r"(b1));
}
__device__ __forceinline__ void cp16(unsigned saddr, const void* gaddr) {
    asm volatile("cp.async.ca.shared.global [%0], [%1], 16;" :: "r"(saddr), "l"(gaddr));
}

template <int C, bool HOUT>
__global__ void __launch_bounds__(256)
gemm_mma(const __half* __restrict__ A, const float* __restrict__ W,
         const float* __restrict__ rnrm, void* __restrict__ out) {
    constexpr int LDA = 136;
    constexpr int LDB = C + 8;
    constexpr int NF = (C / 2) / 8;
    extern __shared__ __half sm16[];
    __half* Ws = sm16;
    __half* As = sm16 + 128 * LDB;
    int tid = threadIdx.x;

    int t0 = blockIdx.x;
    if (t0 < NTILES) {
        const __half* src = A + (size_t)t0 * 64 * 128;
        unsigned sbase = (unsigned)__cvta_generic_to_shared(As);
        #pragma unroll
        for (int q = 0; q < 4; q++) {
            int id = q * 256 + tid;
            int r = id >> 4, c = id & 15;
            cp16(sbase + (r * LDA + c * 8) * 2, src + r * 128 + c * 8);
        }
        asm volatile("cp.async.commit_group;");
    }
    for (int idx = tid; idx < 128 * (C / 4); idx += 256) {
        float4 v = ((const float4*)W)[idx];
        int r = idx / (C / 4), c4 = idx % (C / 4);
        __half2 p0 = __floats2half2_rn(v.x, v.y);
        __half2 p1 = __floats2half2_rn(v.z, v.w);
        uint2 u;
        u.x = *reinterpret_cast<unsigned*>(&p0);
        u.y = *reinterpret_cast<unsigned*>(&p1);
        *(uint2*)(Ws + r * LDB + c4 * 4) = u;
    }
    asm volatile("cp.async.wait_group 0;");
    __syncthreads();

    int wid = tid >> 5, lane = tid & 31;
    int strip = wid & 3;
    int nh = wid >> 2;
    int n_base = nh * (C / 2);
    int a_off = (strip * 16 + (lane & 15)) * LDA + ((lane >> 4) << 3);
    int b_row = lane & 15;

    int buf = 0;
    for (int t = t0; t < NTILES; t += gridDim.x) {
        int tn = t + gridDim.x;
        if (tn < NTILES) {
            const __half* src = A + (size_t)tn * 64 * 128;
            unsigned sbase = (unsigned)__cvta_generic_to_shared(As + (buf ^ 1) * 64 * LDA);
            #pragma unroll
            for (int q = 0; q < 4; q++) {
                int id = q * 256 + tid;
                int r = id >> 4, c = id & 15;
                cp16(sbase + (r * LDA + c * 8) * 2, src + r * 128 + c * 8);
            }
            asm volatile("cp.async.commit_group;");
        }
        float acc[NF][4];
        #pragma unroll
        for (int f = 0; f < NF; f++)
            #pragma unroll
            for (int q = 0; q < 4; q++) acc[f][q] = 0.0f;
        unsigned a_base = (unsigned)__cvta_generic_to_shared(As + buf * 64 * LDA + a_off);
        #pragma unroll
        for (int k0 = 0; k0 < 128; k0 += 16) {
            unsigned a0, a1, a2, a3;
            ldsm_x4(a0, a1, a2, a3, a_base + k0 * 2);
            #pragma unroll
            for (int f = 0; f < NF; f++) {
                unsigned b0, b1;
                unsigned b_addr = (unsigned)__cvta_generic_to_shared(
                    Ws + (k0 + b_row) * LDB + n_base + f * 8);
                ldsm_x2t(b0, b1, b_addr);
                mma16816(acc[f][0], acc[f][1], acc[f][2], acc[f][3], a0, a1, a2, a3, b0, b1);
            }
        }
        int base = t * 64;
        int r0 = base + strip * 16 + (lane >> 2);
        int colb = n_base + (lane & 3) * 2;
        float s0 = (r0 < Nn) ? 1.0f / rnrm[r0] : 0.0f;
        float s1 = (r0 + 8 < Nn) ? 1.0f / rnrm[r0 + 8] : 0.0f;
        #pragma unroll
        for (int f = 0; f < NF; f++) {
            int col = colb + f * 8;
            if (HOUT) {
                __half* o = (__half*)out;
                if (r0 < Nn) {
                    __half2 h = __floats2half2_rn(acc[f][0] * s0, acc[f][1] * s0);
                    *(__half2*)(o + (size_t)r0 * C + col) = h;
                }
                if (r0 + 8 < Nn) {
                    __half2 h = __floats2half2_rn(acc[f][2] * s1, acc[f][3] * s1);
                    *(__half2*)(o + (size_t)(r0 + 8) * C + col) = h;
                }
            } else {
                float* o = (float*)out;
                if (r0 < Nn)
                    *(float2*)(o + (size_t)r0 * C + col) =
                        make_float2(acc[f][0] * s0, acc[f][1] * s0);
                if (r0 + 8 < Nn)
                    *(float2*)(o + (size_t)(r0 + 8) * C + col) =
                        make_float2(acc[f][2] * s1, acc[f][3] * s1);
            }
        }
        asm volatile("cp.async.wait_group 0;");
        __syncthreads();
        buf ^= 1;
    }
}

// ========== fused layer-1 aggregate ==========
__global__ void fused1_kernel(const float* __restrict__ H, const float* __restrict__ b1,
                              const float* __restrict__ lng, const float* __restrict__ lnb,
                              float* __restrict__ O, __half* __restrict__ Oh) {
    int n = (blockIdx.x * blockDim.x + threadIdx.x) >> 5;
    int lane = threadIdx.x & 31;
    if (n >= Nn) return;
    int beg = g_ptr[n], end = g_ptr[n + 1];
    float d2n = g_d2[n];
    float sc = g_cnt[n] * d2n;
    float4 hv = ((const float4*)H)[(size_t)n * 32 + lane];
    float4 acc = make_float4(sc * hv.x, sc * hv.y, sc * hv.z, sc * hv.w);
    for (int i = beg; i < end; i += 4) {
        int m = end - i;
        int i1 = i + (m > 1 ? 1 : 0);
        int i2 = i + (m > 2 ? 2 : 0);
        int i3 = i + (m > 3 ? 3 : 0);
        float w0 = g_w[i];
        float w1 = (m > 1) ? g_w[i1] : 0.0f;
        float w2 = (m > 2) ? g_w[i2] : 0.0f;
        float w3 = (m > 3) ? g_w[i3] : 0.0f;
        int r0 = __ldg(g_srow + i);
        int r1 = __ldg(g_srow + i1);
        int r2 = __ldg(g_srow + i2);
        int r3 = __ldg(g_srow + i3);
        if (w0 != 0.0f) {
            float cf = w0 * g_d2[r0];
            float4 h = ((const float4*)H)[(size_t)r0 * 32 + lane];
            acc.x += cf * h.x; acc.y += cf * h.y; acc.z += cf * h.z; acc.w += cf * h.w;
        }
        if (w1 != 0.0f) {
            float cf = w1 * g_d2[r1];
            float4 h = ((const float4*)H)[(size_t)r1 * 32 + lane];
            acc.x += cf * h.x; acc.y += cf * h.y; acc.z += cf * h.z; acc.w += cf * h.w;
        }
        if (w2 != 0.0f) {
            float cf = w2 * g_d2[r2];
            float4 h = ((const float4*)H)[(size_t)r2 * 32 + lane];
            acc.x += cf * h.x; acc.y += cf * h.y; acc.z += cf * h.z; acc.w += cf * h.w;
        }
        if (w3 != 0.0f) {
            float cf = w3 * g_d2[r3];
            float4 h = ((const float4*)H)[(size_t)r3 * 32 + lane];
            acc.x += cf * h.x; acc.y += cf * h.y; acc.z += cf * h.z; acc.w += cf * h.w;
        }
    }
    float4 bv = ((const float4*)b1)[lane];
    float vx = acc.x * d2n + bv.x, vy = acc.y * d2n + bv.y;
    float vz = acc.z * d2n + bv.z, vw = acc.w * d2n + bv.w;
    float mu = warp_sum(vx + vy + vz + vw) * (1.0f / 128.0f);
    float dx = vx - mu, dy = vy - mu, dz = vz - mu, dw = vw - mu;
    float q = warp_sum(dx * dx + dy * dy + dz * dz + dw * dw);
    float rs = rsqrtf(q * (1.0f / 128.0f) + 1e-5f);
    float4 gv = ((const float4*)lng)[lane];
    float4 ob = ((const float4*)lnb)[lane];
    float4 o;
    o.x = fmaxf(dx * rs * gv.x + ob.x, 0.0f);
    o.y = fmaxf(dy * rs * gv.y + ob.y, 0.0f);
    o.z = fmaxf(dz * rs * gv.z + ob.z, 0.0f);
    o.w = fmaxf(dw * rs * gv.w + ob.w, 0.0f);
    ((float4*)O)[(size_t)n * 32 + lane] = o;
    float ss = warp_sum(o.x * o.x + o.y * o.y + o.z * o.z + o.w * o.w);
    float ri = 1.0f / fmaxf(sqrtf(ss), 1e-8f);
    __half2 h0 = __floats2half2_rn(o.x * ri, o.y * ri);
    __half2 h1 = __floats2half2_rn(o.z * ri, o.w * ri);
    uint2 u;
    u.x = *reinterpret_cast<unsigned int*>(&h0);
    u.y = *reinterpret_cast<unsigned int*>(&h1);
    ((uint2*)Oh)[(size_t)n * 32 + lane] = u;
    if (lane == 0) g_rnrm[n] = ri;
}

// ========== fused layer-2 aggregate (fast exp/log softmax) ==========
__global__ void fused2_kernel(const __half* __restrict__ H, const float* __restrict__ b2,
                              float* __restrict__ out) {
    int n = (blockIdx.x * blockDim.x + threadIdx.x) >> 5;
    int lane = threadIdx.x & 31;
    if (n >= Nn) return;
    int beg = g_ptr[n], end = g_ptr[n + 1];
    float d2n = g_d2[n];
    float sc = g_cnt[n] * d2n;
    const __half2* H2 = (const __half2*)H;
    float2 hv = __half22float2(H2[(size_t)n * 32 + lane]);
    float2 acc = make_float2(sc * hv.x, sc * hv.y);
    int i = beg;
    for (; i + 8 <= end; i += 8) {
        float w[8];
        int r[8];
        #pragma unroll
        for (int u = 0; u < 8; u++) {
            w[u] = g_w[i + u];
            r[u] = __ldg(g_srow + i + u);
        }
        #pragma unroll
        for (int u = 0; u < 8; u++) {
            if (w[u] != 0.0f) {
                float cf = w[u] * g_d2[r[u]];
                float2 h = __half22float2(H2[(size_t)r[u] * 32 + lane]);
                acc.x += cf * h.x; acc.y += cf * h.y;
            }
        }
    }
    for (; i < end; i++) {
        float w = g_w[i];
        if (w != 0.0f) {
            int r = __ldg(g_srow + i);
            float cf = w * g_d2[r];
            float2 h = __half22float2(H2[(size_t)r * 32 + lane]);
            acc.x += cf * h.x; acc.y += cf * h.y;
        }
    }
    float2 bv = ((const float2*)b2)[lane];
    float v0 = acc.x * d2n + bv.x;
    float v1 = acc.y * d2n + bv.y;
    float m = warp_max(fmaxf(v0, v1));
    float s = warp_sum(__expf(v0 - m) + __expf(v1 - m));
    float l = m + __logf(s);
    ((float2*)out)[(size_t)n * 32 + lane] = make_float2(v0 - l, v1 - l);
}

// ======================= launch ==============================
extern "C" void kernel_launch(void* const* d_in, const int* in_sizes, int n_in,
                              void* d_out, int out_size) {
    const float* x   = (const float*)d_in[0];
    const int*   row = (const int*)d_in[1];
    const int*   col = (const int*)d_in[2];
    const float* W1  = (const float*)d_in[3];
    const float* b1  = (const float*)d_in[4];
    const float* lng = (const float*)d_in[5];
    const float* lnb = (const float*)d_in[6];
    const float* W2  = (const float*)d_in[7];
    const float* b2  = (const float*)d_in[8];
    float* out = (float*)d_out;

    void *p_h, *p_acc, *p_xh, *p_rn, *p_dra, *p_drb, *p_hist, *p_flag;
    cudaGetSymbolAddress(&p_h, g_h);
    cudaGetSymbolAddress(&p_acc, g_acc);
    cudaGetSymbolAddress(&p_xh, g_xh);
    cudaGetSymbolAddress(&p_rn, g_rnrm);
    cudaGetSymbolAddress(&p_dra, g_dra);
    cudaGetSymbolAddress(&p_drb, g_drb);
    cudaGetSymbolAddress(&p_hist, g_hist);
    cudaGetSymbolAddress(&p_flag, g_flag);
    float* gh = (float*)p_h;
    float* gacc = (float*)p_acc;
    __half* gxh = (__half*)p_xh;
    __half* ghh = (__half*)p_h;
    float* grn = (float*)p_rn;
    float* dra = (float*)p_dra;
    float* drb = (float*)p_drb;

    static cudaStream_t s1 = nullptr;
    static cudaEvent_t evStart, evRN, evG1, evF2, evG2;
    if (s1 == nullptr) {
        cudaStreamCreateWithFlags(&s1, cudaStreamNonBlocking);
        cudaEventCreateWithFlags(&evStart, cudaEventDisableTiming);
        cudaEventCreateWithFlags(&evRN, cudaEventDisableTiming);
        cudaEventCreateWithFlags(&evG1, cudaEventDisableTiming);
        cudaEventCreateWithFlags(&evF2, cudaEventDisableTiming);
        cudaEventCreateWithFlags(&evG2, cudaEventDisableTiming);
    }

    const size_t smem1 = (size_t)(128 * 136 + 2 * 64 * 136) * sizeof(__half);
    const size_t smem2 = (size_t)(128 * 72 + 2 * 64 * 136) * sizeof(__half);
    cudaFuncSetAttribute((gemm_mma<128, false>), cudaFuncAttributeMaxDynamicSharedMemorySize, (int)smem1);
    cudaFuncSetAttribute((gemm_mma<64, true>),   cudaFuncAttributeMaxDynamicSharedMemorySize, (int)smem2);

    // ---- upfront zeroing (s0) ----
    cudaMemsetAsync(p_hist, 0, NSCAN * sizeof(int));
    cudaMemsetAsync(p_flag, 0, SCAN_B * sizeof(int));
    cudaMemsetAsync(p_dra,  0, Nn * sizeof(float));
    cudaMemsetAsync(p_drb,  0, Nn * sizeof(float));
    cudaEventRecord(evStart, 0);

    // ---- CSC build on s0 || rnrm+GEMM1 on s1 ----
    hist_kernel<<<NB_EDGE_T, 256>>>(col);                               // k1 (s0)
    scan_lookback_kernel<<<SCAN_B, 1024>>>();                           // k2 (s0)
    cudaStreamWaitEvent(s1, evStart, 0);
    rnrm_kernel<<<NB_NODE_W, 256, 0, s1>>>(x, gxh);                     // k3 (s1)
    cudaEventRecord(evRN, s1);
    scatter_kernel<<<NB_EDGE_T, 256>>>(row, col);                       // k4 (s0) <- profiled
    gemm_mma<128, false><<<NB_G1, 256, smem1, s1>>>(gxh, W1, grn, gh);  // k5 (s1)
    cudaEventRecord(evG1, s1);

    // ---- layer-1 attention (s0; needs scatter + rnrm) ----
    cudaStreamWaitEvent(0, evRN, 0);
    edge_dot_h<<<NB_NODE_W, 256>>>(gxh, x, dra);                        // k6
    edge_w_kernel<<<NB_NODE_W, 256>>>(dra);                             // k7
    cudaStreamWaitEvent(0, evG1, 0);
    fused1_kernel<<<NB_NODE_W, 256>>>(gh, b1, lng, lnb, gacc, gxh);     // k8

    // ---- layer 2 ----
    cudaEventRecord(evF2, 0);
    cudaStreamWaitEvent(s1, evF2, 0);
    gemm_mma<64, true><<<NB_G2, 256, smem2, s1>>>(gxh, W2, grn, ghh);   // k9 (s1)
    cudaEventRecord(evG2, s1);

    edge_dot_h<<<NB_NODE_W, 256>>>(gxh, gacc, drb);                     // k10
    edge_w_kernel<<<NB_NODE_W, 256>>>(drb);                             // k11
    cudaStreamWaitEvent(0, evG2, 0);
    fused2_kernel<<<NB_NODE_W, 256>>>(ghh, b2, out);                    // k12
}

// round 16
// speedup vs baseline: 1.1029x; 1.1029x over previous
#include <cuda_runtime.h>
#include <cuda_fp16.h>
#include <math.h>

#define Nn 100000
#define Ee 1600000
#define NSCAN (Nn + 1)
#define FIX_MARGIN 3e-3f
#define NB_SCATTER 6250      // Ee/256
#define NB_NODE_W 12500      // Nn*32/256
#define SCAN_B 98            // ceil(100001/1024)
#define NTILES 1563          // ceil(Nn/64)
#define NB_G1 444            // persistent gemm grid (C=128)
#define NB_G2 592            // persistent gemm grid (C=64)

// ---------------- scratch (__device__ globals; no runtime allocation) ----------------
__device__ __align__(16) float g_h[(size_t)Nn * 128];       // h1 ; layer2: hW2 as fp16
__device__ __align__(16) float g_acc[(size_t)Nn * 128];     // relu(LN(...)) of layer 1
__device__ __align__(16) __half g_xh[(size_t)(Nn + 64) * 128]; // NORMALIZED fp16 (padded)
__device__ __align__(16) float g_w[Ee];                     // sims (CSC order)
__device__ __align__(16) float2 g_cwr[Ee];                  // compacted (weight, row) pairs
__device__ int g_srow[Ee];
__device__ int g_hist[NSCAN];                               // hist; then g_kc (kept counts)
__device__ int g_ptr[NSCAN];
__device__ int g_pos[Nn];
__device__ int g_agg[SCAN_B];
__device__ int g_flag[SCAN_B];
__device__ float g_rnrm[Nn];                                // 1/max(||f||, eps)
__device__ float g_dra[Nn];
__device__ float g_drb[Nn];
__device__ float g_cnt[Nn];
__device__ float g_d2[Nn];

__device__ __forceinline__ float warp_sum(float v) {
    #pragma unroll
    for (int o = 16; o; o >>= 1) v += __shfl_xor_sync(0xFFFFFFFFu, v, o);
    return v;
}
__device__ __forceinline__ int warp_isum(int v) {
    #pragma unroll
    for (int o = 16; o; o >>= 1) v += __shfl_xor_sync(0xFFFFFFFFu, v, o);
    return v;
}
__device__ __forceinline__ float warp_max(float v) {
    #pragma unroll
    for (int o = 16; o; o >>= 1) v = fmaxf(v, __shfl_xor_sync(0xFFFFFFFFu, v, o));
    return v;
}

// ======================= CSC build (R14 structure, measured best) ==================
__global__ void hist_kernel(const int* __restrict__ col) {
    int e = blockIdx.x * blockDim.x + threadIdx.x;
    if (e < Ee) atomicAdd(&g_hist[__ldg(col + e)], 1);
}

__global__ void scan_lookback_kernel() {
    __shared__ int wsum[32];
    __shared__ int s_off;
    int tid = threadIdx.x;
    int lane = tid & 31, wid = tid >> 5;
    int b = blockIdx.x;
    int i = b * 1024 + tid;
    int v = (i < NSCAN) ? g_hist[i] : 0;
    int x = v;
    #pragma unroll
    for (int o = 1; o < 32; o <<= 1) {
        int t = __shfl_up_sync(0xFFFFFFFFu, x, o);
        if (lane >= o) x += t;
    }
    if (lane == 31) wsum[wid] = x;
    __syncthreads();
    if (wid == 0) {
        int y = wsum[lane];
        #pragma unroll
        for (int o = 1; o < 32; o <<= 1) {
            int t = __shfl_up_sync(0xFFFFFFFFu, y, o);
            if (lane >= o) y += t;
        }
        wsum[lane] = y;
    }
    __syncthreads();
    int incl = x + (wid ? wsum[wid - 1] : 0);
    if (tid == 0) {
        g_agg[b] = wsum[31];
        __threadfence();
        *((volatile int*)&g_flag[b]) = 1;
    }
    if (tid < 32) {
        volatile int* flag = g_flag;
        volatile int* agg  = g_agg;
        int acc = 0;
        for (int j = lane; j < b; j += 32) {
            while (flag[j] == 0) { }
            acc += agg[j];
        }
        acc = warp_isum(acc);
        if (lane == 0) s_off = acc;
    }
    __syncthreads();
    int excl = incl - v + s_off;
    if (i < NSCAN) {
        g_ptr[i] = excl;
        if (i < Nn) g_pos[i] = excl;
    }
}

__global__ void scatter_rnrm_kernel(const int* __restrict__ row, const int* __restrict__ col,
                                    const float* __restrict__ F, __half* __restrict__ Fh) {
    if (blockIdx.x < NB_SCATTER) {
        int e = blockIdx.x * 256 + threadIdx.x;
        if (e >= Ee) return;
        int c = __ldg(col + e);
        int p = atomicAdd(&g_pos[c], 1);
        g_srow[p] = __ldg(row + e);
    } else {
        int n = ((blockIdx.x - NB_SCATTER) * 256 + threadIdx.x) >> 5;
        int lane = threadIdx.x & 31;
        if (n >= Nn) return;
        float4 v = ((const float4*)F)[(size_t)n * 32 + lane];
        float ss = warp_sum(v.x * v.x + v.y * v.y + v.z * v.z + v.w * v.w);
        float ri = 1.0f / fmaxf(sqrtf(ss), 1e-8f);
        __half2 h0 = __floats2half2_rn(v.x * ri, v.y * ri);
        __half2 h1 = __floats2half2_rn(v.z * ri, v.w * ri);
        uint2 u;
        u.x = *reinterpret_cast<unsigned int*>(&h0);
        u.y = *reinterpret_cast<unsigned int*>(&h1);
        ((uint2*)Fh)[(size_t)n * 32 + lane] = u;
        if (lane == 0) g_rnrm[n] = ri;
    }
}

// ======================= edge similarity ====================
__device__ __forceinline__ float dot16h2(const uint4& a0, const uint4& a1,
                                         const __half2* fc) {
    __half2 acc = __hmul2(*(const __half2*)&a0.x, fc[0]);
    acc = __hfma2(*(const __half2*)&a0.y, fc[1], acc);
    acc = __hfma2(*(const __half2*)&a0.z, fc[2], acc);
    acc = __hfma2(*(const __half2*)&a0.w, fc[3], acc);
    acc = __hfma2(*(const __half2*)&a1.x, fc[4], acc);
    acc = __hfma2(*(const __half2*)&a1.y, fc[5], acc);
    acc = __hfma2(*(const __half2*)&a1.z, fc[6], acc);
    acc = __hfma2(*(const __half2*)&a1.w, fc[7], acc);
    float2 f = __half22float2(acc);
    return f.x + f.y;
}

__global__ void __launch_bounds__(256, 6)
edge_dot_h(const __half* __restrict__ Fh, const float* __restrict__ F,
           float* __restrict__ dr) {
    int n = (blockIdx.x * blockDim.x + threadIdx.x) >> 5;
    int lane = threadIdx.x & 31;
    if (n >= Nn) return;
    int k = lane & 7;
    int g = lane >> 3;
    unsigned gmask = 0xFFu << (g * 8);
    const uint4* F16 = (const uint4*)Fh;
    uint4 c0 = F16[(size_t)n * 16 + k];
    uint4 c1 = F16[(size_t)n * 16 + k + 8];
    __half2 fc[8];
    fc[0] = *(const __half2*)&c0.x; fc[1] = *(const __half2*)&c0.y;
    fc[2] = *(const __half2*)&c0.z; fc[3] = *(const __half2*)&c0.w;
    fc[4] = *(const __half2*)&c1.x; fc[5] = *(const __half2*)&c1.y;
    fc[6] = *(const __half2*)&c1.z; fc[7] = *(const __half2*)&c1.w;
    int beg = g_ptr[n], end = g_ptr[n + 1];
    for (int i = beg; i < end; i += 4) {
        int j = i + g;
        bool valid = j < end;
        int r = __ldg(g_srow + (valid ? j : end - 1));
        uint4 a0 = F16[(size_t)r * 16 + k];
        uint4 a1 = F16[(size_t)r * 16 + k + 8];
        float s = dot16h2(a0, a1, fc);
        s += __shfl_xor_sync(0xFFFFFFFFu, s, 4);
        s += __shfl_xor_sync(0xFFFFFFFFu, s, 2);
        s += __shfl_xor_sync(0xFFFFFFFFu, s, 1);
        float sim = s;
        if (valid && fabsf(sim - 0.1f) < FIX_MARGIN) {
            const float4* Fr = (const float4*)(F + (size_t)r * 128);
            const float4* Fc = (const float4*)(F + (size_t)n * 128);
            float4 xa = Fr[k],      ya = Fc[k];
            float4 xb = Fr[k + 8],  yb = Fc[k + 8];
            float4 xd = Fr[k + 16], yd = Fc[k + 16];
            float4 xe = Fr[k + 24], ye = Fc[k + 24];
            float t = xa.x * ya.x + xa.y * ya.y + xa.z * ya.z + xa.w * ya.w
                    + xb.x * yb.x + xb.y * yb.y + xb.z * yb.z + xb.w * yb.w
                    + xd.x * yd.x + xd.y * yd.y + xd.z * yd.z + xd.w * yd.w
                    + xe.x * ye.x + xe.y * ye.y + xe.z * ye.z + xe.w * ye.w;
            t += __shfl_xor_sync(gmask, t, 4);
            t += __shfl_xor_sync(gmask, t, 2);
            t += __shfl_xor_sync(gmask, t, 1);
            sim = t * g_rnrm[r] * g_rnrm[n];
        }
        if (valid && k == 0) {
            if (sim >= 0.1f) { g_w[j] = sim; atomicAdd(dr + r, sim); }
            else g_w[j] = 0.0f;
        }
    }
}

// fast-exp edge weights + COMPACTION of kept (w, row) pairs + selfw + dinv2
__global__ void edge_w_kernel(const float* __restrict__ dr) {
    int n = (blockIdx.x * blockDim.x + threadIdx.x) >> 5;
    int lane = threadIdx.x & 31;
    if (n >= Nn) return;
    int beg = g_ptr[n], end = g_ptr[n + 1];
    float d = dr[n];
    float dc = (d > 0.0f) ? rsqrtf(d) : 0.0f;
    float deg2 = 0.0f;
    int base = 0;                                   // compaction cursor (warp-uniform)
    unsigned lt = (1u << lane) - 1u;
    for (int c = beg; c < end; c += 32) {
        int i = c + lane;
        bool in = i < end;
        float s = in ? g_w[i] : 0.0f;
        bool kept = s > 0.0f;
        float w = 0.0f;
        int r = 0;
        if (kept) {
            r = __ldg(g_srow + i);
            w = __expf(rsqrtf(dr[r]) * s * dc);
            deg2 += w;
        }
        unsigned m = __ballot_sync(0xFFFFFFFFu, kept);
        if (kept) {
            int pos = base + __popc(m & lt);
            g_cwr[beg + pos] = make_float2(w, __int_as_float(r));
        }
        base += __popc(m);
    }
    deg2 = warp_sum(deg2);
    if (lane == 0) {
        float selfw = __expf(1.0f / (float)(base + 1));
        g_cnt[n] = selfw;
        g_d2[n] = rsqrtf(deg2 + selfw);
        g_hist[n] = base;                           // kept count (g_hist dead after scan)
    }
}

// ======================= persistent tensor-core GEMM ==================================
__device__ __forceinline__ void ldsm_x4(unsigned& a0, unsigned& a1, unsigned& a2, unsigned& a3,
                                        unsigned addr) {
    asm volatile("ldmatrix.sync.aligned.m8n8.x4.shared.b16 {%0,%1,%2,%3}, [%4];"
                 : "=r"(a0), "=r"(a1), "=r"(a2), "=r"(a3) : "r"(addr));
}
__device__ __forceinline__ void ldsm_x2t(unsigned& b0, unsigned& b1, unsigned addr) {
    asm volatile("ldmatrix.sync.aligned.m8n8.x2.trans.shared.b16 {%0,%1}, [%2];"
                 : "=r"(b0), "=r"(b1) : "r"(addr));
}
__device__ __forceinline__ void mma16816(float& d0, float& d1, float& d2, float& d3,
                                         unsigned a0, unsigned a1, unsigned a2, unsigned a3,
                                         unsigned b0, unsigned b1) {
    asm volatile("mma.sync.aligned.m16n8k16.row.col.f32.f16.f16.f32 "
                 "{%0,%1,%2,%3}, {%4,%5,%6,%7}, {%8,%9}, {%0,%1,%2,%3};"
                 : "+f"(d0), "+f"(d1), "+f"(d2), "+f"(d3)
                 : "r"(a0), "r"(a1), "r"(a2), "r"(a3), "r"(b0), "r"(b1));
}
__device__ __forceinline__ void cp16(unsigned saddr, const void* gaddr) {
    asm volatile("cp.async.ca.shared.global [%0], [%1], 16;" :: "r"(saddr), "l"(gaddr));
}

template <int C, bool HOUT>
__global__ void __launch_bounds__(256)
gemm_mma(const __half* __restrict__ A, const float* __restrict__ W,
         const float* __restrict__ rnrm, void* __restrict__ out) {
    constexpr int LDA = 136;
    constexpr int LDB = C + 8;
    constexpr int NF = (C / 2) / 8;
    extern __shared__ __half sm16[];
    __half* Ws = sm16;
    __half* As = sm16 + 128 * LDB;
    int tid = threadIdx.x;

    int t0 = blockIdx.x;
    if (t0 < NTILES) {
        const __half* src = A + (size_t)t0 * 64 * 128;
        unsigned sbase = (unsigned)__cvta_generic_to_shared(As);
        #pragma unroll
        for (int q = 0; q < 4; q++) {
            int id = q * 256 + tid;
            int r = id >> 4, c = id & 15;
            cp16(sbase + (r * LDA + c * 8) * 2, src + r * 128 + c * 8);
        }
        asm volatile("cp.async.commit_group;");
    }
    for (int idx = tid; idx < 128 * (C / 4); idx += 256) {
        float4 v = ((const float4*)W)[idx];
        int r = idx / (C / 4), c4 = idx % (C / 4);
        __half2 p0 = __floats2half2_rn(v.x, v.y);
        __half2 p1 = __floats2half2_rn(v.z, v.w);
        uint2 u;
        u.x = *reinterpret_cast<unsigned*>(&p0);
        u.y = *reinterpret_cast<unsigned*>(&p1);
        *(uint2*)(Ws + r * LDB + c4 * 4) = u;
    }
    asm volatile("cp.async.wait_group 0;");
    __syncthreads();

    int wid = tid >> 5, lane = tid & 31;
    int strip = wid & 3;
    int nh = wid >> 2;
    int n_base = nh * (C / 2);
    int a_off = (strip * 16 + (lane & 15)) * LDA + ((lane >> 4) << 3);
    int b_row = lane & 15;

    int buf = 0;
    for (int t = t0; t < NTILES; t += gridDim.x) {
        int tn = t + gridDim.x;
        if (tn < NTILES) {
            const __half* src = A + (size_t)tn * 64 * 128;
            unsigned sbase = (unsigned)__cvta_generic_to_shared(As + (buf ^ 1) * 64 * LDA);
            #pragma unroll
            for (int q = 0; q < 4; q++) {
                int id = q * 256 + tid;
                int r = id >> 4, c = id & 15;
                cp16(sbase + (r * LDA + c * 8) * 2, src + r * 128 + c * 8);
            }
            asm volatile("cp.async.commit_group;");
        }
        float acc[NF][4];
        #pragma unroll
        for (int f = 0; f < NF; f++)
            #pragma unroll
            for (int q = 0; q < 4; q++) acc[f][q] = 0.0f;
        unsigned a_base = (unsigned)__cvta_generic_to_shared(As + buf * 64 * LDA + a_off);
        #pragma unroll
        for (int k0 = 0; k0 < 128; k0 += 16) {
            unsigned a0, a1, a2, a3;
            ldsm_x4(a0, a1, a2, a3, a_base + k0 * 2);
            #pragma unroll
            for (int f = 0; f < NF; f++) {
                unsigned b0, b1;
                unsigned b_addr = (unsigned)__cvta_generic_to_shared(
                    Ws + (k0 + b_row) * LDB + n_base + f * 8);
                ldsm_x2t(b0, b1, b_addr);
                mma16816(acc[f][0], acc[f][1], acc[f][2], acc[f][3], a0, a1, a2, a3, b0, b1);
            }
        }
        int base = t * 64;
        int r0 = base + strip * 16 + (lane >> 2);
        int colb = n_base + (lane & 3) * 2;
        float s0 = (r0 < Nn) ? 1.0f / rnrm[r0] : 0.0f;
        float s1 = (r0 + 8 < Nn) ? 1.0f / rnrm[r0 + 8] : 0.0f;
        #pragma unroll
        for (int f = 0; f < NF; f++) {
            int col = colb + f * 8;
            if (HOUT) {
                __half* o = (__half*)out;
                if (r0 < Nn) {
                    __half2 h = __floats2half2_rn(acc[f][0] * s0, acc[f][1] * s0);
                    *(__half2*)(o + (size_t)r0 * C + col) = h;
                }
                if (r0 + 8 < Nn) {
                    __half2 h = __floats2half2_rn(acc[f][2] * s1, acc[f][3] * s1);
                    *(__half2*)(o + (size_t)(r0 + 8) * C + col) = h;
                }
            } else {
                float* o = (float*)out;
                if (r0 < Nn)
                    *(float2*)(o + (size_t)r0 * C + col) =
                        make_float2(acc[f][0] * s0, acc[f][1] * s0);
                if (r0 + 8 < Nn)
                    *(float2*)(o + (size_t)(r0 + 8) * C + col) =
                        make_float2(acc[f][2] * s1, acc[f][3] * s1);
            }
        }
        asm volatile("cp.async.wait_group 0;");
        __syncthreads();
        buf ^= 1;
    }
}

// ========== fused layer-1 aggregate: compacted gather + self + b1 + LN + ReLU ==========
__global__ void fused1_kernel(const float* __restrict__ H, const float* __restrict__ b1,
                              const float* __restrict__ lng, const float* __restrict__ lnb,
                              float* __restrict__ O, __half* __restrict__ Oh) {
    int n = (blockIdx.x * blockDim.x + threadIdx.x) >> 5;
    int lane = threadIdx.x & 31;
    if (n >= Nn) return;
    int beg = g_ptr[n];
    int kend = beg + g_hist[n];                 // kept edges only
    float d2n = g_d2[n];
    float sc = g_cnt[n] * d2n;
    float4 hv = ((const float4*)H)[(size_t)n * 32 + lane];
    float4 acc = make_float4(sc * hv.x, sc * hv.y, sc * hv.z, sc * hv.w);
    for (int i = beg; i < kend; i += 4) {
        int m = kend - i;
        float2 e0 = g_cwr[i];
        float2 e1 = (m > 1) ? g_cwr[i + 1] : make_float2(0.f, 0.f);
        float2 e2 = (m > 2) ? g_cwr[i + 2] : make_float2(0.f, 0.f);
        float2 e3 = (m > 3) ? g_cwr[i + 3] : make_float2(0.f, 0.f);
        {
            int r = __float_as_int(e0.y);
            float cf = e0.x * g_d2[r];
            float4 h = ((const float4*)H)[(size_t)r * 32 + lane];
            acc.x += cf * h.x; acc.y += cf * h.y; acc.z += cf * h.z; acc.w += cf * h.w;
        }
        if (m > 1) {
            int r = __float_as_int(e1.y);
            float cf = e1.x * g_d2[r];
            float4 h = ((const float4*)H)[(size_t)r * 32 + lane];
            acc.x += cf * h.x; acc.y += cf * h.y; acc.z += cf * h.z; acc.w += cf * h.w;
        }
        if (m > 2) {
            int r = __float_as_int(e2.y);
            float cf = e2.x * g_d2[r];
            float4 h = ((const float4*)H)[(size_t)r * 32 + lane];
            acc.x += cf * h.x; acc.y += cf * h.y; acc.z += cf * h.z; acc.w += cf * h.w;
        }
        if (m > 3) {
            int r = __float_as_int(e3.y);
            float cf = e3.x * g_d2[r];
            float4 h = ((const float4*)H)[(size_t)r * 32 + lane];
            acc.x += cf * h.x; acc.y += cf * h.y; acc.z += cf * h.z; acc.w += cf * h.w;
        }
    }
    float4 bv = ((const float4*)b1)[lane];
    float vx = acc.x * d2n + bv.x, vy = acc.y * d2n + bv.y;
    float vz = acc.z * d2n + bv.z, vw = acc.w * d2n + bv.w;
    float mu = warp_sum(vx + vy + vz + vw) * (1.0f / 128.0f);
    float dx = vx - mu, dy = vy - mu, dz = vz - mu, dw = vw - mu;
    float q = warp_sum(dx * dx + dy * dy + dz * dz + dw * dw);
    float rs = rsqrtf(q * (1.0f / 128.0f) + 1e-5f);
    float4 gv = ((const float4*)lng)[lane];
    float4 ob = ((const float4*)lnb)[lane];
    float4 o;
    o.x = fmaxf(dx * rs * gv.x + ob.x, 0.0f);
    o.y = fmaxf(dy * rs * gv.y + ob.y, 0.0f);
    o.z = fmaxf(dz * rs * gv.z + ob.z, 0.0f);
    o.w = fmaxf(dw * rs * gv.w + ob.w, 0.0f);
    ((float4*)O)[(size_t)n * 32 + lane] = o;
    float ss = warp_sum(o.x * o.x + o.y * o.y + o.z * o.z + o.w * o.w);
    float ri = 1.0f / fmaxf(sqrtf(ss), 1e-8f);
    __half2 h0 = __floats2half2_rn(o.x * ri, o.y * ri);
    __half2 h1 = __floats2half2_rn(o.z * ri, o.w * ri);
    uint2 u;
    u.x = *reinterpret_cast<unsigned int*>(&h0);
    u.y = *reinterpret_cast<unsigned int*>(&h1);
    ((uint2*)Oh)[(size_t)n * 32 + lane] = u;
    if (lane == 0) g_rnrm[n] = ri;
}

// ========== fused layer-2 aggregate: compacted fp16 gather + log_softmax ==========
__global__ void fused2_kernel(const __half* __restrict__ H, const float* __restrict__ b2,
                              float* __restrict__ out) {
    int n = (blockIdx.x * blockDim.x + threadIdx.x) >> 5;
    int lane = threadIdx.x & 31;
    if (n >= Nn) return;
    int beg = g_ptr[n];
    int kend = beg + g_hist[n];
    float d2n = g_d2[n];
    float sc = g_cnt[n] * d2n;
    const __half2* H2 = (const __half2*)H;
    float2 hv = __half22float2(H2[(size_t)n * 32 + lane]);
    float2 acc = make_float2(sc * hv.x, sc * hv.y);
    int i = beg;
    for (; i + 8 <= kend; i += 8) {
        float2 e[8];
        #pragma unroll
        for (int u = 0; u < 8; u++) e[u] = g_cwr[i + u];
        #pragma unroll
        for (int u = 0; u < 8; u++) {
            int r = __float_as_int(e[u].y);
            float cf = e[u].x * g_d2[r];
            float2 h = __half22float2(H2[(size_t)r * 32 + lane]);
            acc.x += cf * h.x; acc.y += cf * h.y;
        }
    }
    for (; i < kend; i++) {
        float2 e = g_cwr[i];
        int r = __float_as_int(e.y);
        float cf = e.x * g_d2[r];
        float2 h = __half22float2(H2[(size_t)r * 32 + lane]);
        acc.x += cf * h.x; acc.y += cf * h.y;
    }
    float2 bv = ((const float2*)b2)[lane];
    float v0 = acc.x * d2n + bv.x;
    float v1 = acc.y * d2n + bv.y;
    float m = warp_max(fmaxf(v0, v1));
    float s = warp_sum(__expf(v0 - m) + __expf(v1 - m));
    float l = m + __logf(s);
    ((float2*)out)[(size_t)n * 32 + lane] = make_float2(v0 - l, v1 - l);
}

// ======================= launch ==============================
extern "C" void kernel_launch(void* const* d_in, const int* in_sizes, int n_in,
                              void* d_out, int out_size) {
    const float* x   = (const float*)d_in[0];
    const int*   row = (const int*)d_in[1];
    const int*   col = (const int*)d_in[2];
    const float* W1  = (const float*)d_in[3];
    const float* b1  = (const float*)d_in[4];
    const float* lng = (const float*)d_in[5];
    const float* lnb = (const float*)d_in[6];
    const float* W2  = (const float*)d_in[7];
    const float* b2  = (const float*)d_in[8];
    float* out = (float*)d_out;

    void *p_h, *p_acc, *p_xh, *p_rn, *p_dra, *p_drb, *p_hist, *p_flag;
    cudaGetSymbolAddress(&p_h, g_h);
    cudaGetSymbolAddress(&p_acc, g_acc);
    cudaGetSymbolAddress(&p_xh, g_xh);
    cudaGetSymbolAddress(&p_rn, g_rnrm);
    cudaGetSymbolAddress(&p_dra, g_dra);
    cudaGetSymbolAddress(&p_drb, g_drb);
    cudaGetSymbolAddress(&p_hist, g_hist);
    cudaGetSymbolAddress(&p_flag, g_flag);
    float* gh = (float*)p_h;
    float* gacc = (float*)p_acc;
    __half* gxh = (__half*)p_xh;
    __half* ghh = (__half*)p_h;
    float* grn = (float*)p_rn;
    float* dra = (float*)p_dra;
    float* drb = (float*)p_drb;

    static cudaStream_t s1 = nullptr;
    static cudaEvent_t evF1, evG1, evF2, evG2;
    if (s1 == nullptr) {
        cudaStreamCreateWithFlags(&s1, cudaStreamNonBlocking);
        cudaEventCreateWithFlags(&evF1, cudaEventDisableTiming);
        cudaEventCreateWithFlags(&evG1, cudaEventDisableTiming);
        cudaEventCreateWithFlags(&evF2, cudaEventDisableTiming);
        cudaEventCreateWithFlags(&evG2, cudaEventDisableTiming);
    }

    const size_t smem1 = (size_t)(128 * 136 + 2 * 64 * 136) * sizeof(__half);
    const size_t smem2 = (size_t)(128 * 72 + 2 * 64 * 136) * sizeof(__half);
    cudaFuncSetAttribute((gemm_mma<128, false>), cudaFuncAttributeMaxDynamicSharedMemorySize, (int)smem1);
    cudaFuncSetAttribute((gemm_mma<64, true>),   cudaFuncAttributeMaxDynamicSharedMemorySize, (int)smem2);

    const int NB_EDGE_T = (Ee + 255) / 256;

    // ---- upfront zeroing ----
    cudaMemsetAsync(p_hist, 0, NSCAN * sizeof(int));
    cudaMemsetAsync(p_flag, 0, SCAN_B * sizeof(int));
    cudaMemsetAsync(p_dra,  0, Nn * sizeof(float));
    cudaMemsetAsync(p_drb,  0, Nn * sizeof(float));

    // ---- CSC build + prep (stream 0) ----
    hist_kernel<<<NB_EDGE_T, 256>>>(col);                               // 1
    scan_lookback_kernel<<<SCAN_B, 1024>>>();                           // 2
    scatter_rnrm_kernel<<<NB_SCATTER + NB_NODE_W, 256>>>(row, col, x, gxh); // 3
    cudaEventRecord(evF1, 0);     // g_xh + g_rnrm ready

    // ---- layer-1 attention ----
    edge_dot_h<<<NB_NODE_W, 256>>>(gxh, x, dra);                        // 4 <- profiled

    // GEMM1 on s1 (reads g_xh + g_rnrm), overlaps edge_dot/edge_w
    cudaStreamWaitEvent(s1, evF1, 0);
    gemm_mma<128, false><<<NB_G1, 256, smem1, s1>>>(gxh, W1, grn, gh);  // 5
    cudaEventRecord(evG1, s1);

    edge_w_kernel<<<NB_NODE_W, 256>>>(dra);                             // 6
    cudaStreamWaitEvent(0, evG1, 0);
    fused1_kernel<<<NB_NODE_W, 256>>>(gh, b1, lng, lnb, gacc, gxh);     // 7

    // ---- layer 2 ----
    cudaEventRecord(evF2, 0);
    cudaStreamWaitEvent(s1, evF2, 0);
    gemm_mma<64, true><<<NB_G2, 256, smem2, s1>>>(gxh, W2, grn, ghh);   // 8
    cudaEventRecord(evG2, s1);

    edge_dot_h<<<NB_NODE_W, 256>>>(gxh, gacc, drb);                     // 9
    edge_w_kernel<<<NB_NODE_W, 256>>>(drb);                             // 10
    cudaStreamWaitEvent(0, evG2, 0);
    fused2_kernel<<<NB_NODE_W, 256>>>(ghh, b2, out);                    // 11
}

// round 17
// speedup vs baseline: 1.1224x; 1.0176x over previous
#include <cuda_runtime.h>
#include <cuda_fp16.h>
#include <math.h>

#define Nn 100000
#define Ee 1600000
#define NSCAN (Nn + 1)
#define FIX_MARGIN 3e-3f
#define NB_SCATTER 6250      // Ee/256
#define NB_NODE_W 12500      // Nn*32/256
#define SCAN_B 98            // ceil(100001/1024)
#define NTILES 1563          // ceil(Nn/64)
#define NB_G1 444            // persistent gemm grid (C=128)
#define NB_G2 592            // persistent gemm grid (C=64)

// ---------------- scratch (__device__ globals; no runtime allocation) ----------------
__device__ __align__(16) float g_h[(size_t)Nn * 128];       // h1 ; layer2: hW2 as fp16
__device__ __align__(16) float g_acc[(size_t)Nn * 128];     // relu(LN(...)) of layer 1
__device__ __align__(16) __half g_xh[(size_t)(Nn + 64) * 128]; // NORMALIZED fp16 (padded)
__device__ __align__(16) float g_w[Ee];                     // sims (CSC order)
__device__ __align__(16) float2 g_cwr[Ee];                  // compacted (weight, row) pairs
__device__ int g_srow[Ee];
__device__ int g_hist[NSCAN];                               // hist; then kept counts
__device__ int g_ptr[NSCAN];
__device__ int g_pos[Nn];
__device__ int g_agg[SCAN_B];
__device__ int g_flag[SCAN_B];
__device__ float g_rnrm[Nn];                                // 1/max(||f||, eps)
__device__ float g_dra[Nn];
__device__ float g_drb[Nn];
__device__ float g_cnt[Nn];
__device__ float g_d2[Nn];

__device__ __forceinline__ float warp_sum(float v) {
    #pragma unroll
    for (int o = 16; o; o >>= 1) v += __shfl_xor_sync(0xFFFFFFFFu, v, o);
    return v;
}
__device__ __forceinline__ int warp_isum(int v) {
    #pragma unroll
    for (int o = 16; o; o >>= 1) v += __shfl_xor_sync(0xFFFFFFFFu, v, o);
    return v;
}
__device__ __forceinline__ float warp_max(float v) {
    #pragma unroll
    for (int o = 16; o; o >>= 1) v = fmaxf(v, __shfl_xor_sync(0xFFFFFFFFu, v, o));
    return v;
}

// ======================= CSC build ==================
__global__ void hist_kernel(const int* __restrict__ col) {
    int e = blockIdx.x * blockDim.x + threadIdx.x;
    if (e < Ee) atomicAdd(&g_hist[__ldg(col + e)], 1);
}

__global__ void scan_lookback_kernel() {
    __shared__ int wsum[32];
    __shared__ int s_off;
    int tid = threadIdx.x;
    int lane = tid & 31, wid = tid >> 5;
    int b = blockIdx.x;
    int i = b * 1024 + tid;
    int v = (i < NSCAN) ? g_hist[i] : 0;
    int x = v;
    #pragma unroll
    for (int o = 1; o < 32; o <<= 1) {
        int t = __shfl_up_sync(0xFFFFFFFFu, x, o);
        if (lane >= o) x += t;
    }
    if (lane == 31) wsum[wid] = x;
    __syncthreads();
    if (wid == 0) {
        int y = wsum[lane];
        #pragma unroll
        for (int o = 1; o < 32; o <<= 1) {
            int t = __shfl_up_sync(0xFFFFFFFFu, y, o);
            if (lane >= o) y += t;
        }
        wsum[lane] = y;
    }
    __syncthreads();
    int incl = x + (wid ? wsum[wid - 1] : 0);
    if (tid == 0) {
        g_agg[b] = wsum[31];
        __threadfence();
        *((volatile int*)&g_flag[b]) = 1;
    }
    if (tid < 32) {
        volatile int* flag = g_flag;
        volatile int* agg  = g_agg;
        int acc = 0;
        for (int j = lane; j < b; j += 32) {
            while (flag[j] == 0) { }
            acc += agg[j];
        }
        acc = warp_isum(acc);
        if (lane == 0) s_off = acc;
    }
    __syncthreads();
    int excl = incl - v + s_off;
    if (i < NSCAN) {
        g_ptr[i] = excl;
        if (i < Nn) g_pos[i] = excl;
    }
}

__global__ void scatter_rnrm_kernel(const int* __restrict__ row, const int* __restrict__ col,
                                    const float* __restrict__ F, __half* __restrict__ Fh) {
    if (blockIdx.x < NB_SCATTER) {
        int e = blockIdx.x * 256 + threadIdx.x;
        if (e >= Ee) return;
        int c = __ldg(col + e);
        int p = atomicAdd(&g_pos[c], 1);
        g_srow[p] = __ldg(row + e);
    } else {
        int n = ((blockIdx.x - NB_SCATTER) * 256 + threadIdx.x) >> 5;
        int lane = threadIdx.x & 31;
        if (n >= Nn) return;
        float4 v = ((const float4*)F)[(size_t)n * 32 + lane];
        float ss = warp_sum(v.x * v.x + v.y * v.y + v.z * v.z + v.w * v.w);
        float ri = 1.0f / fmaxf(sqrtf(ss), 1e-8f);
        __half2 h0 = __floats2half2_rn(v.x * ri, v.y * ri);
        __half2 h1 = __floats2half2_rn(v.z * ri, v.w * ri);
        uint2 u;
        u.x = *reinterpret_cast<unsigned int*>(&h0);
        u.y = *reinterpret_cast<unsigned int*>(&h1);
        ((uint2*)Fh)[(size_t)n * 32 + lane] = u;
        if (lane == 0) g_rnrm[n] = ri;
    }
}

// ======================= edge similarity ====================
__device__ __forceinline__ float dot16h2(const uint4& a0, const uint4& a1,
                                         const __half2* fc) {
    __half2 acc = __hmul2(*(const __half2*)&a0.x, fc[0]);
    acc = __hfma2(*(const __half2*)&a0.y, fc[1], acc);
    acc = __hfma2(*(const __half2*)&a0.z, fc[2], acc);
    acc = __hfma2(*(const __half2*)&a0.w, fc[3], acc);
    acc = __hfma2(*(const __half2*)&a1.x, fc[4], acc);
    acc = __hfma2(*(const __half2*)&a1.y, fc[5], acc);
    acc = __hfma2(*(const __half2*)&a1.z, fc[6], acc);
    acc = __hfma2(*(const __half2*)&a1.w, fc[7], acc);
    float2 f = __half22float2(acc);
    return f.x + f.y;
}

// occupancy experiment: force 8 blocks/SM (regs <= 32; cold fixup path may spill)
__global__ void __launch_bounds__(256, 8)
edge_dot_h(const __half* __restrict__ Fh, const float* __restrict__ F,
           float* __restrict__ dr) {
    int n = (blockIdx.x * blockDim.x + threadIdx.x) >> 5;
    int lane = threadIdx.x & 31;
    if (n >= Nn) return;
    int k = lane & 7;
    int g = lane >> 3;
    unsigned gmask = 0xFFu << (g * 8);
    const uint4* F16 = (const uint4*)Fh;
    uint4 c0 = F16[(size_t)n * 16 + k];
    uint4 c1 = F16[(size_t)n * 16 + k + 8];
    __half2 fc[8];
    fc[0] = *(const __half2*)&c0.x; fc[1] = *(const __half2*)&c0.y;
    fc[2] = *(const __half2*)&c0.z; fc[3] = *(const __half2*)&c0.w;
    fc[4] = *(const __half2*)&c1.x; fc[5] = *(const __half2*)&c1.y;
    fc[6] = *(const __half2*)&c1.z; fc[7] = *(const __half2*)&c1.w;
    int beg = g_ptr[n], end = g_ptr[n + 1];
    for (int i = beg; i < end; i += 4) {
        int j = i + g;
        bool valid = j < end;
        int r = __ldg(g_srow + (valid ? j : end - 1));
        uint4 a0 = F16[(size_t)r * 16 + k];
        uint4 a1 = F16[(size_t)r * 16 + k + 8];
        float s = dot16h2(a0, a1, fc);
        s += __shfl_xor_sync(0xFFFFFFFFu, s, 4);
        s += __shfl_xor_sync(0xFFFFFFFFu, s, 2);
        s += __shfl_xor_sync(0xFFFFFFFFu, s, 1);
        float sim = s;
        if (valid && fabsf(sim - 0.1f) < FIX_MARGIN) {
            const float4* Fr = (const float4*)(F + (size_t)r * 128);
            const float4* Fc = (const float4*)(F + (size_t)n * 128);
            float4 xa = Fr[k],      ya = Fc[k];
            float4 xb = Fr[k + 8],  yb = Fc[k + 8];
            float4 xd = Fr[k + 16], yd = Fc[k + 16];
            float4 xe = Fr[k + 24], ye = Fc[k + 24];
            float t = xa.x * ya.x + xa.y * ya.y + xa.z * ya.z + xa.w * ya.w
                    + xb.x * yb.x + xb.y * yb.y + xb.z * yb.z + xb.w * yb.w
                    + xd.x * yd.x + xd.y * yd.y + xd.z * yd.z + xd.w * yd.w
                    + xe.x * ye.x + xe.y * ye.y + xe.z * ye.z + xe.w * ye.w;
            t += __shfl_xor_sync(gmask, t, 4);
            t += __shfl_xor_sync(gmask, t, 2);
            t += __shfl_xor_sync(gmask, t, 1);
            sim = t * g_rnrm[r] * g_rnrm[n];
        }
        if (valid && k == 0) {
            if (sim >= 0.1f) { g_w[j] = sim; atomicAdd(dr + r, sim); }
            else g_w[j] = 0.0f;
        }
    }
}

// fast-exp edge weights + COMPACTION of kept (w, row) pairs + selfw + dinv2
__global__ void edge_w_kernel(const float* __restrict__ dr) {
    int n = (blockIdx.x * blockDim.x + threadIdx.x) >> 5;
    int lane = threadIdx.x & 31;
    if (n >= Nn) return;
    int beg = g_ptr[n], end = g_ptr[n + 1];
    float d = dr[n];
    float dc = (d > 0.0f) ? rsqrtf(d) : 0.0f;
    float deg2 = 0.0f;
    int base = 0;
    unsigned lt = (1u << lane) - 1u;
    for (int c = beg; c < end; c += 32) {
        int i = c + lane;
        bool in = i < end;
        float s = in ? g_w[i] : 0.0f;
        bool kept = s > 0.0f;
        float w = 0.0f;
        int r = 0;
        if (kept) {
            r = __ldg(g_srow + i);
            w = __expf(rsqrtf(dr[r]) * s * dc);
            deg2 += w;
        }
        unsigned m = __ballot_sync(0xFFFFFFFFu, kept);
        if (kept) {
            int pos = base + __popc(m & lt);
            g_cwr[beg + pos] = make_float2(w, __int_as_float(r));
        }
        base += __popc(m);
    }
    deg2 = warp_sum(deg2);
    if (lane == 0) {
        float selfw = __expf(1.0f / (float)(base + 1));
        g_cnt[n] = selfw;
        g_d2[n] = rsqrtf(deg2 + selfw);
        g_hist[n] = base;
    }
}

// ======================= persistent tensor-core GEMM ==================================
__device__ __forceinline__ void ldsm_x4(unsigned& a0, unsigned& a1, unsigned& a2, unsigned& a3,
                                        unsigned addr) {
    asm volatile("ldmatrix.sync.aligned.m8n8.x4.shared.b16 {%0,%1,%2,%3}, [%4];"
                 : "=r"(a0), "=r"(a1), "=r"(a2), "=r"(a3) : "r"(addr));
}
__device__ __forceinline__ void ldsm_x2t(unsigned& b0, unsigned& b1, unsigned addr) {
    asm volatile("ldmatrix.sync.aligned.m8n8.x2.trans.shared.b16 {%0,%1}, [%2];"
                 : "=r"(b0), "=r"(b1) : "r"(addr));
}
__device__ __forceinline__ void mma16816(float& d0, float& d1, float& d2, float& d3,
                                         unsigned a0, unsigned a1, unsigned a2, unsigned a3,
                                         unsigned b0, unsigned b1) {
    asm volatile("mma.sync.aligned.m16n8k16.row.col.f32.f16.f16.f32 "
                 "{%0,%1,%2,%3}, {%4,%5,%6,%7}, {%8,%9}, {%0,%1,%2,%3};"
                 : "+f"(d0), "+f"(d1), "+f"(d2), "+f"(d3)
                 : "r"(a0), "r"(a1), "r"(a2), "r"(a3), "r"(b0), "r"(b1));
}
__device__ __forceinline__ void cp16(unsigned saddr, const void* gaddr) {
    asm volatile("cp.async.ca.shared.global [%0], [%1], 16;" :: "r"(saddr), "l"(gaddr));
}

template <int C, bool HOUT>
__global__ void __launch_bounds__(256)
gemm_mma(const __half* __restrict__ A, const float* __restrict__ W,
         const float* __restrict__ rnrm, void* __restrict__ out) {
    constexpr int LDA = 136;
    constexpr int LDB = C + 8;
    constexpr int NF = (C / 2) / 8;
    extern __shared__ __half sm16[];
    __half* Ws = sm16;
    __half* As = sm16 + 128 * LDB;
    int tid = threadIdx.x;

    int t0 = blockIdx.x;
    if (t0 < NTILES) {
        const __half* src = A + (size_t)t0 * 64 * 128;
        unsigned sbase = (unsigned)__cvta_generic_to_shared(As);
        #pragma unroll
        for (int q = 0; q < 4; q++) {
            int id = q * 256 + tid;
            int r = id >> 4, c = id & 15;
            cp16(sbase + (r * LDA + c * 8) * 2, src + r * 128 + c * 8);
        }
        asm volatile("cp.async.commit_group;");
    }
    for (int idx = tid; idx < 128 * (C / 4); idx += 256) {
        float4 v = ((const float4*)W)[idx];
        int r = idx / (C / 4), c4 = idx % (C / 4);
        __half2 p0 = __floats2half2_rn(v.x, v.y);
        __half2 p1 = __floats2half2_rn(v.z, v.w);
        uint2 u;
        u.x = *reinterpret_cast<unsigned*>(&p0);
        u.y = *reinterpret_cast<unsigned*>(&p1);
        *(uint2*)(Ws + r * LDB + c4 * 4) = u;
    }
    asm volatile("cp.async.wait_group 0;");
    __syncthreads();

    int wid = tid >> 5, lane = tid & 31;
    int strip = wid & 3;
    int nh = wid >> 2;
    int n_base = nh * (C / 2);
    int a_off = (strip * 16 + (lane & 15)) * LDA + ((lane >> 4) << 3);
    int b_row = lane & 15;

    int buf = 0;
    for (int t = t0; t < NTILES; t += gridDim.x) {
        int tn = t + gridDim.x;
        if (tn < NTILES) {
            const __half* src = A + (size_t)tn * 64 * 128;
            unsigned sbase = (unsigned)__cvta_generic_to_shared(As + (buf ^ 1) * 64 * LDA);
            #pragma unroll
            for (int q = 0; q < 4; q++) {
                int id = q * 256 + tid;
                int r = id >> 4, c = id & 15;
                cp16(sbase + (r * LDA + c * 8) * 2, src + r * 128 + c * 8);
            }
            asm volatile("cp.async.commit_group;");
        }
        float acc[NF][4];
        #pragma unroll
        for (int f = 0; f < NF; f++)
            #pragma unroll
            for (int q = 0; q < 4; q++) acc[f][q] = 0.0f;
        unsigned a_base = (unsigned)__cvta_generic_to_shared(As + buf * 64 * LDA + a_off);
        #pragma unroll
        for (int k0 = 0; k0 < 128; k0 += 16) {
            unsigned a0, a1, a2, a3;
            ldsm_x4(a0, a1, a2, a3, a_base + k0 * 2);
            #pragma unroll
            for (int f = 0; f < NF; f++) {
                unsigned b0, b1;
                unsigned b_addr = (unsigned)__cvta_generic_to_shared(
                    Ws + (k0 + b_row) * LDB + n_base + f * 8);
                ldsm_x2t(b0, b1, b_addr);
                mma16816(acc[f][0], acc[f][1], acc[f][2], acc[f][3], a0, a1, a2, a3, b0, b1);
            }
        }
        int base = t * 64;
        int r0 = base + strip * 16 + (lane >> 2);
        int colb = n_base + (lane & 3) * 2;
        float s0 = (r0 < Nn) ? 1.0f / rnrm[r0] : 0.0f;
        float s1 = (r0 + 8 < Nn) ? 1.0f / rnrm[r0 + 8] : 0.0f;
        #pragma unroll
        for (int f = 0; f < NF; f++) {
            int col = colb + f * 8;
            if (HOUT) {
                __half* o = (__half*)out;
                if (r0 < Nn) {
                    __half2 h = __floats2half2_rn(acc[f][0] * s0, acc[f][1] * s0);
                    *(__half2*)(o + (size_t)r0 * C + col) = h;
                }
                if (r0 + 8 < Nn) {
                    __half2 h = __floats2half2_rn(acc[f][2] * s1, acc[f][3] * s1);
                    *(__half2*)(o + (size_t)(r0 + 8) * C + col) = h;
                }
            } else {
                float* o = (float*)out;
                if (r0 < Nn)
                    *(float2*)(o + (size_t)r0 * C + col) =
                        make_float2(acc[f][0] * s0, acc[f][1] * s0);
                if (r0 + 8 < Nn)
                    *(float2*)(o + (size_t)(r0 + 8) * C + col) =
                        make_float2(acc[f][2] * s1, acc[f][3] * s1);
            }
        }
        asm volatile("cp.async.wait_group 0;");
        __syncthreads();
        buf ^= 1;
    }
}

// ========== fused layer-1 aggregate: compacted gather + self + b1 + LN + ReLU ==========
__global__ void fused1_kernel(const float* __restrict__ H, const float* __restrict__ b1,
                              const float* __restrict__ lng, const float* __restrict__ lnb,
                              float* __restrict__ O, __half* __restrict__ Oh) {
    int n = (blockIdx.x * blockDim.x + threadIdx.x) >> 5;
    int lane = threadIdx.x & 31;
    if (n >= Nn) return;
    int beg = g_ptr[n];
    int kend = beg + g_hist[n];
    float d2n = g_d2[n];
    float sc = g_cnt[n] * d2n;
    float4 hv = ((const float4*)H)[(size_t)n * 32 + lane];
    float4 acc = make_float4(sc * hv.x, sc * hv.y, sc * hv.z, sc * hv.w);
    for (int i = beg; i < kend; i += 4) {
        int m = kend - i;
        float2 e0 = g_cwr[i];
        float2 e1 = (m > 1) ? g_cwr[i + 1] : make_float2(0.f, 0.f);
        float2 e2 = (m > 2) ? g_cwr[i + 2] : make_float2(0.f, 0.f);
        float2 e3 = (m > 3) ? g_cwr[i + 3] : make_float2(0.f, 0.f);
        {
            int r = __float_as_int(e0.y);
            float cf = e0.x * g_d2[r];
            float4 h = ((const float4*)H)[(size_t)r * 32 + lane];
            acc.x += cf * h.x; acc.y += cf * h.y; acc.z += cf * h.z; acc.w += cf * h.w;
        }
        if (m > 1) {
            int r = __float_as_int(e1.y);
            float cf = e1.x * g_d2[r];
            float4 h = ((const float4*)H)[(size_t)r * 32 + lane];
            acc.x += cf * h.x; acc.y += cf * h.y; acc.z += cf * h.z; acc.w += cf * h.w;
        }
        if (m > 2) {
            int r = __float_as_int(e2.y);
            float cf = e2.x * g_d2[r];
            float4 h = ((const float4*)H)[(size_t)r * 32 + lane];
            acc.x += cf * h.x; acc.y += cf * h.y; acc.z += cf * h.z; acc.w += cf * h.w;
        }
        if (m > 3) {
            int r = __float_as_int(e3.y);
            float cf = e3.x * g_d2[r];
            float4 h = ((const float4*)H)[(size_t)r * 32 + lane];
            acc.x += cf * h.x; acc.y += cf * h.y; acc.z += cf * h.z; acc.w += cf * h.w;
        }
    }
    float4 bv = ((const float4*)b1)[lane];
    float vx = acc.x * d2n + bv.x, vy = acc.y * d2n + bv.y;
    float vz = acc.z * d2n + bv.z, vw = acc.w * d2n + bv.w;
    float mu = warp_sum(vx + vy + vz + vw) * (1.0f / 128.0f);
    float dx = vx - mu, dy = vy - mu, dz = vz - mu, dw = vw - mu;
    float q = warp_sum(dx * dx + dy * dy + dz * dz + dw * dw);
    float rs = rsqrtf(q * (1.0f / 128.0f) + 1e-5f);
    float4 gv = ((const float4*)lng)[lane];
    float4 ob = ((const float4*)lnb)[lane];
    float4 o;
    o.x = fmaxf(dx * rs * gv.x + ob.x, 0.0f);
    o.y = fmaxf(dy * rs * gv.y + ob.y, 0.0f);
    o.z = fmaxf(dz * rs * gv.z + ob.z, 0.0f);
    o.w = fmaxf(dw * rs * gv.w + ob.w, 0.0f);
    ((float4*)O)[(size_t)n * 32 + lane] = o;
    float ss = warp_sum(o.x * o.x + o.y * o.y + o.z * o.z + o.w * o.w);
    float ri = 1.0f / fmaxf(sqrtf(ss), 1e-8f);
    __half2 h0 = __floats2half2_rn(o.x * ri, o.y * ri);
    __half2 h1 = __floats2half2_rn(o.z * ri, o.w * ri);
    uint2 u;
    u.x = *reinterpret_cast<unsigned int*>(&h0);
    u.y = *reinterpret_cast<unsigned int*>(&h1);
    ((uint2*)Oh)[(size_t)n * 32 + lane] = u;
    if (lane == 0) g_rnrm[n] = ri;
}

// ========== fused layer-2 aggregate: compacted fp16 gather + log_softmax ==========
__global__ void fused2_kernel(const __half* __restrict__ H, const float* __restrict__ b2,
                              float* __restrict__ out) {
    int n = (blockIdx.x * blockDim.x + threadIdx.x) >> 5;
    int lane = threadIdx.x & 31;
    if (n >= Nn) return;
    int beg = g_ptr[n];
    int kend = beg + g_hist[n];
    float d2n = g_d2[n];
    float sc = g_cnt[n] * d2n;
    const __half2* H2 = (const __half2*)H;
    float2 hv = __half22float2(H2[(size_t)n * 32 + lane]);
    float2 acc = make_float2(sc * hv.x, sc * hv.y);
    int i = beg;
    for (; i + 8 <= kend; i += 8) {
        float2 e[8];
        #pragma unroll
        for (int u = 0; u < 8; u++) e[u] = g_cwr[i + u];
        #pragma unroll
        for (int u = 0; u < 8; u++) {
            int r = __float_as_int(e[u].y);
            float cf = e[u].x * g_d2[r];
            float2 h = __half22float2(H2[(size_t)r * 32 + lane]);
            acc.x += cf * h.x; acc.y += cf * h.y;
        }
    }
    for (; i < kend; i++) {
        float2 e = g_cwr[i];
        int r = __float_as_int(e.y);
        float cf = e.x * g_d2[r];
        float2 h = __half22float2(H2[(size_t)r * 32 + lane]);
        acc.x += cf * h.x; acc.y += cf * h.y;
    }
    float2 bv = ((const float2*)b2)[lane];
    float v0 = acc.x * d2n + bv.x;
    float v1 = acc.y * d2n + bv.y;
    float m = warp_max(fmaxf(v0, v1));
    float s = warp_sum(__expf(v0 - m) + __expf(v1 - m));
    float l = m + __logf(s);
    ((float2*)out)[(size_t)n * 32 + lane] = make_float2(v0 - l, v1 - l);
}

// ======================= launch ==============================
extern "C" void kernel_launch(void* const* d_in, const int* in_sizes, int n_in,
                              void* d_out, int out_size) {
    const float* x   = (const float*)d_in[0];
    const int*   row = (const int*)d_in[1];
    const int*   col = (const int*)d_in[2];
    const float* W1  = (const float*)d_in[3];
    const float* b1  = (const float*)d_in[4];
    const float* lng = (const float*)d_in[5];
    const float* lnb = (const float*)d_in[6];
    const float* W2  = (const float*)d_in[7];
    const float* b2  = (const float*)d_in[8];
    float* out = (float*)d_out;

    void *p_h, *p_acc, *p_xh, *p_rn, *p_dra, *p_drb, *p_hist, *p_flag;
    cudaGetSymbolAddress(&p_h, g_h);
    cudaGetSymbolAddress(&p_acc, g_acc);
    cudaGetSymbolAddress(&p_xh, g_xh);
    cudaGetSymbolAddress(&p_rn, g_rnrm);
    cudaGetSymbolAddress(&p_dra, g_dra);
    cudaGetSymbolAddress(&p_drb, g_drb);
    cudaGetSymbolAddress(&p_hist, g_hist);
    cudaGetSymbolAddress(&p_flag, g_flag);
    float* gh = (float*)p_h;
    float* gacc = (float*)p_acc;
    __half* gxh = (__half*)p_xh;
    __half* ghh = (__half*)p_h;
    float* grn = (float*)p_rn;
    float* dra = (float*)p_dra;
    float* drb = (float*)p_drb;

    static cudaStream_t s1 = nullptr;
    static cudaEvent_t evF1, evG1, evF2, evG2;
    if (s1 == nullptr) {
        cudaStreamCreateWithFlags(&s1, cudaStreamNonBlocking);
        cudaEventCreateWithFlags(&evF1, cudaEventDisableTiming);
        cudaEventCreateWithFlags(&evG1, cudaEventDisableTiming);
        cudaEventCreateWithFlags(&evF2, cudaEventDisableTiming);
        cudaEventCreateWithFlags(&evG2, cudaEventDisableTiming);
    }

    const size_t smem1 = (size_t)(128 * 136 + 2 * 64 * 136) * sizeof(__half);
    const size_t smem2 = (size_t)(128 * 72 + 2 * 64 * 136) * sizeof(__half);
    cudaFuncSetAttribute((gemm_mma<128, false>), cudaFuncAttributeMaxDynamicSharedMemorySize, (int)smem1);
    cudaFuncSetAttribute((gemm_mma<64, true>),   cudaFuncAttributeMaxDynamicSharedMemorySize, (int)smem2);

    const int NB_EDGE_T = (Ee + 255) / 256;

    // ---- upfront zeroing ----
    cudaMemsetAsync(p_hist, 0, NSCAN * sizeof(int));
    cudaMemsetAsync(p_flag, 0, SCAN_B * sizeof(int));
    cudaMemsetAsync(p_dra,  0, Nn * sizeof(float));
    cudaMemsetAsync(p_drb,  0, Nn * sizeof(float));

    // ---- CSC build + prep (stream 0) ----
    hist_kernel<<<NB_EDGE_T, 256>>>(col);                               // 1
    scan_lookback_kernel<<<SCAN_B, 1024>>>();                           // 2
    scatter_rnrm_kernel<<<NB_SCATTER + NB_NODE_W, 256>>>(row, col, x, gxh); // 3
    cudaEventRecord(evF1, 0);     // g_xh + g_rnrm ready

    // ---- layer-1 attention ----
    edge_dot_h<<<NB_NODE_W, 256>>>(gxh, x, dra);                        // 4 <- profiled

    // GEMM1 on s1 (reads g_xh + g_rnrm), overlaps edge_dot/edge_w
    cudaStreamWaitEvent(s1, evF1, 0);
    gemm_mma<128, false><<<NB_G1, 256, smem1, s1>>>(gxh, W1, grn, gh);  // 5
    cudaEventRecord(evG1, s1);

    edge_w_kernel<<<NB_NODE_W, 256>>>(dra);                             // 6
    cudaStreamWaitEvent(0, evG1, 0);
    fused1_kernel<<<NB_NODE_W, 256>>>(gh, b1, lng, lnb, gacc, gxh);     // 7

    // ---- layer 2 ----
    cudaEventRecord(evF2, 0);
    cudaStreamWaitEvent(s1, evF2, 0);
    gemm_mma<64, true><<<NB_G2, 256, smem2, s1>>>(gxh, W2, grn, ghh);   // 8
    cudaEventRecord(evG2, s1);

    edge_dot_h<<<NB_NODE_W, 256>>>(gxh, gacc, drb);                     // 9
    edge_w_kernel<<<NB_NODE_W, 256>>>(drb);                             // 10
    cudaStreamWaitEvent(0, evG2, 0);
    fused2_kernel<<<NB_NODE_W, 256>>>(ghh, b2, out);                    // 11
}